// round 13
// baseline (speedup 1.0000x reference)
#include <cuda_runtime.h>
#include <cstdint>

#define NB 4
#define NUM_OP 6
#define LANG_DIM 256
#define NHIDDEN 128
#define HH 128
#define WW 128
#define HWSZ (HH * WW)        // 16384
#define NC 128
#define SEM_CH (NUM_OP + 2)   // 8

#define CCHUNK 16
#define TPB 512
#define GRID_X (HWSZ / 4 / TPB)     // 8
#define GRID_Z (NC / CCHUNK)        // 8   -> 256 blocks x 512 threads
#define TOTAL_BLOCKS (GRID_X * NB * GRID_Z)  // 256
#define N_PROD 32

__device__ float4 g_actv4[NB][NHIDDEN / 4];
__device__ int    g_ready;   // producers done counter (reset each run)
__device__ int    g_done;    // completion counter (reset each run)

__device__ __forceinline__ float dot4(float4 a, float4 b) {
    return a.x * b.x + a.y * b.y + a.z * b.z + a.w * b.w;
}

__device__ __forceinline__ float4 ldcg4(const float4* p) {
    float4 v;
    asm volatile("ld.global.cg.v4.f32 {%0,%1,%2,%3}, [%4];"
                 : "=f"(v.x), "=f"(v.y), "=f"(v.z), "=f"(v.w) : "l"(p));
    return v;
}

// ---------------------------------------------------------------------------
// Single fused kernel. Grid (8,4,8) = 256 blocks x 512 threads, one wave.
//  - Blocks 0..31 (flat id) additionally produce 4 actv rows each (warps 0-7).
//  - All blocks: sem loads first -> spin for producers (hidden) -> per-block
//    fold (L2 reads, __ldcg) -> stream 16 channels (R12 body).
//  - Last block resets counters for graph replay.
// ---------------------------------------------------------------------------
__global__ __launch_bounds__(TPB) void fused_kernel(
    const float* __restrict__ x,
    const float* __restrict__ lang,
    const float* __restrict__ sem,
    const float* __restrict__ Ws, const float* __restrict__ bs,
    const float* __restrict__ Wg, const float* __restrict__ bg,
    const float* __restrict__ Wb, const float* __restrict__ bb,
    const float* __restrict__ Wr, const float* __restrict__ br,
    float* __restrict__ out) {
    const int tid  = threadIdx.x;
    const int warp = tid >> 5;
    const int lane = tid & 31;
    const int b    = blockIdx.y;
    const int c0   = blockIdx.z * CCHUNK;
    const int hw4  = blockIdx.x * TPB + tid;   // [0, HWSZ/4)
    const int fb   = blockIdx.x + GRID_X * (blockIdx.y + NB * blockIdx.z);

    __shared__ float s_gw[NUM_OP], s_bw[NUM_OP];
    __shared__ float s_wrsum, s_br;

    // 1) Issue the 6 semantic loads immediately (independent of everything).
    const float4* semb =
        reinterpret_cast<const float4*>(sem + (size_t)b * SEM_CH * HWSZ + 2 * HWSZ) + hw4;
    float4 sv[NUM_OP];
#pragma unroll
    for (int k = 0; k < NUM_OP; ++k)
        sv[k] = __ldg(semb + (size_t)k * (HWSZ / 4));

    // 2) Producer duty: blocks 0..31 compute 4 actv rows each (warps 0-7).
    if (fb < N_PROD) {
        if (warp < 8) {
            const int n  = 4 * fb + (warp >> 1);
            const int b0 = (warp & 1) * 2;
            const float4* Ws4   = reinterpret_cast<const float4*>(Ws) + (size_t)n * (LANG_DIM / 4);
            const float4* lang4 = reinterpret_cast<const float4*>(lang);

            float p0 = 0.0f, p1 = 0.0f;
#pragma unroll
            for (int i = 0; i < 2; ++i) {
                const int idx = lane + 32 * i;
                const float4 wv = Ws4[idx];
                p0 += dot4(wv, lang4[(size_t)b0 * (LANG_DIM / 4) + idx]);
                p1 += dot4(wv, lang4[(size_t)(b0 + 1) * (LANG_DIM / 4) + idx]);
            }
#pragma unroll
            for (int off = 16; off > 0; off >>= 1) {
                p0 += __shfl_xor_sync(0xFFFFFFFFu, p0, off);
                p1 += __shfl_xor_sync(0xFFFFFFFFu, p1, off);
            }
            if (lane == 0) {
                const float bias = bs[n];
                reinterpret_cast<float*>(g_actv4[b0])[n]     = p0 + bias;
                reinterpret_cast<float*>(g_actv4[b0 + 1])[n] = p1 + bias;
            }
        }
        __syncthreads();
        if (tid == 0) {
            __threadfence();
            atomicAdd(&g_ready, 1);
        }
    }

    // 3) Wait for all producers (overlapped with in-flight sem loads).
    if (tid == 0) {
        volatile int* vr = &g_ready;
        while (*vr < N_PROD) __nanosleep(32);
        __threadfence();
    }
    __syncthreads();

    // 4) Per-block fold (warps 0-6; g_actv4 via .cg to bypass L1).
    if (warp < NUM_OP) {
        const int k = warp;
        const float4 a  = ldcg4(&g_actv4[b][lane]);
        const float4 wg = reinterpret_cast<const float4*>(Wg)[(size_t)k * (NHIDDEN / 4) + lane];
        const float4 wb = reinterpret_cast<const float4*>(Wb)[(size_t)k * (NHIDDEN / 4) + lane];
        float pg = dot4(a, wg);
        float pb = dot4(a, wb);
#pragma unroll
        for (int off = 16; off > 0; off >>= 1) {
            pg += __shfl_xor_sync(0xFFFFFFFFu, pg, off);
            pb += __shfl_xor_sync(0xFFFFFFFFu, pb, off);
        }
        if (lane == 0) {
            const float wr = Wr[k];
            s_gw[k] = (pg + bg[k]) * wr;
            s_bw[k] = (pb + bb[k]) * wr;
        }
    } else if (warp == 7 && lane == 0) {
        float s = 0.0f;
#pragma unroll
        for (int k = 0; k < NUM_OP; ++k) s += Wr[k];
        s_wrsum = s;
        s_br = br[0];
    }
    __syncthreads();

    // 5) Combine (first consumption of sv -> scoreboard wait lands here).
    float4 scale = make_float4(s_wrsum, s_wrsum, s_wrsum, s_wrsum);
    float4 shift = make_float4(s_br, s_br, s_br, s_br);
#pragma unroll
    for (int k = 0; k < NUM_OP; ++k) {
        const float gw = s_gw[k];
        const float bw = s_bw[k];
        scale.x += gw * sv[k].x;  scale.y += gw * sv[k].y;
        scale.z += gw * sv[k].z;  scale.w += gw * sv[k].w;
        shift.x += bw * sv[k].x;  shift.y += bw * sv[k].y;
        shift.z += bw * sv[k].z;  shift.w += bw * sv[k].w;
    }

    // 6) Stream 16 channels of x -> out (R12 body).
    const float4* xb = reinterpret_cast<const float4*>(x + (size_t)b * NC * HWSZ) + hw4;
    float4*       ob = reinterpret_cast<float4*>(out + (size_t)b * NC * HWSZ) + hw4;

#pragma unroll 8
    for (int c = c0; c < c0 + CCHUNK; ++c) {
        float4 xv = xb[(size_t)c * (HWSZ / 4)];
        float4 o;
        o.x = xv.x * scale.x + shift.x;
        o.y = xv.y * scale.y + shift.y;
        o.z = xv.z * scale.z + shift.z;
        o.w = xv.w * scale.w + shift.w;
        ob[(size_t)c * (HWSZ / 4)] = o;
    }

    // 7) Last block resets sync state for the next graph replay.
    __syncthreads();
    if (tid == 0) {
        if (atomicAdd(&g_done, 1) == TOTAL_BLOCKS - 1) {
            g_ready = 0;
            g_done  = 0;
            __threadfence();
        }
    }
}

// ---------------------------------------------------------------------------
extern "C" void kernel_launch(void* const* d_in, const int* in_sizes, int n_in,
                              void* d_out, int out_size) {
    const float* x    = (const float*)d_in[0];
    const float* lang = (const float*)d_in[1];
    const float* sem  = (const float*)d_in[2];
    const float* Ws   = (const float*)d_in[3];
    const float* bs   = (const float*)d_in[4];
    const float* Wg   = (const float*)d_in[5];
    const float* bg   = (const float*)d_in[6];
    const float* Wb   = (const float*)d_in[7];
    const float* bb   = (const float*)d_in[8];
    const float* Wr   = (const float*)d_in[9];
    const float* br   = (const float*)d_in[10];
    float* out = (float*)d_out;

    dim3 grid(GRID_X, NB, GRID_Z);
    fused_kernel<<<grid, TPB>>>(x, lang, sem, Ws, bs, Wg, bg, Wb, bb, Wr, br, out);
}

// round 15
// speedup vs baseline: 1.1032x; 1.1032x over previous
#include <cuda_runtime.h>
#include <cstdint>

#define NB 4
#define NUM_OP 6
#define LANG_DIM 256
#define NHIDDEN 128
#define HH 128
#define WW 128
#define HWSZ (HH * WW)        // 16384
#define NC 128
#define SEM_CH (NUM_OP + 2)   // 8

#define CCHUNK 8
#define TPB 512
#define GRID_X (HWSZ / 8 / TPB)     // 4   (each thread: 8 contiguous floats)
#define GRID_Z (NC / CCHUNK)        // 16  -> 256 blocks x 512 threads

__device__ float4 g_actv4[NB][NHIDDEN / 4];

__device__ __forceinline__ float dot4(float4 a, float4 b) {
    return a.x * b.x + a.y * b.y + a.z * b.z + a.w * b.w;
}

// 256-bit L2 evict-last load: 8 floats per thread, read set pinned in L2.
__device__ __forceinline__ void ld_el8(const float* p, float4& lo, float4& hi) {
    uint64_t r0, r1, r2, r3;
    asm volatile("ld.global.nc.L2::evict_last.v4.b64 {%0,%1,%2,%3}, [%4];"
                 : "=l"(r0), "=l"(r1), "=l"(r2), "=l"(r3) : "l"(p));
    lo.x = __uint_as_float((uint32_t)r0);  lo.y = __uint_as_float((uint32_t)(r0 >> 32));
    lo.z = __uint_as_float((uint32_t)r1);  lo.w = __uint_as_float((uint32_t)(r1 >> 32));
    hi.x = __uint_as_float((uint32_t)r2);  hi.y = __uint_as_float((uint32_t)(r2 >> 32));
    hi.z = __uint_as_float((uint32_t)r3);  hi.w = __uint_as_float((uint32_t)(r3 >> 32));
}

// 256-bit L2 evict-first store: write-once stream passes through L2.
__device__ __forceinline__ void st_ef8(float* p, float4 lo, float4 hi) {
    uint64_t r0 = (uint64_t)__float_as_uint(lo.x) | ((uint64_t)__float_as_uint(lo.y) << 32);
    uint64_t r1 = (uint64_t)__float_as_uint(lo.z) | ((uint64_t)__float_as_uint(lo.w) << 32);
    uint64_t r2 = (uint64_t)__float_as_uint(hi.x) | ((uint64_t)__float_as_uint(hi.y) << 32);
    uint64_t r3 = (uint64_t)__float_as_uint(hi.z) | ((uint64_t)__float_as_uint(hi.w) << 32);
    asm volatile("st.global.L2::evict_first.v4.b64 [%0], {%1,%2,%3,%4};"
                 :: "l"(p), "l"(r0), "l"(r1), "l"(r2), "l"(r3) : "memory");
}

// ---------------------------------------------------------------------------
// K1: actv[b][n] = bs[n] + lang[b,:].Ws[n,:]  — 32 blocks x 256 threads.
// ---------------------------------------------------------------------------
__global__ __launch_bounds__(256) void actv_kernel(
    const float* __restrict__ lang,
    const float* __restrict__ Ws, const float* __restrict__ bs) {
    const int warp = threadIdx.x >> 5;
    const int lane = threadIdx.x & 31;
    const int n  = 4 * blockIdx.x + (warp >> 1);
    const int b0 = (warp & 1) * 2;

    const float4* Ws4   = reinterpret_cast<const float4*>(Ws) + (size_t)n * (LANG_DIM / 4);
    const float4* lang4 = reinterpret_cast<const float4*>(lang);

    float p0 = 0.0f, p1 = 0.0f;
#pragma unroll
    for (int i = 0; i < 2; ++i) {
        const int idx = lane + 32 * i;
        const float4 wv = Ws4[idx];
        p0 += dot4(wv, lang4[(size_t)b0 * (LANG_DIM / 4) + idx]);
        p1 += dot4(wv, lang4[(size_t)(b0 + 1) * (LANG_DIM / 4) + idx]);
    }
#pragma unroll
    for (int off = 16; off > 0; off >>= 1) {
        p0 += __shfl_xor_sync(0xFFFFFFFFu, p0, off);
        p1 += __shfl_xor_sync(0xFFFFFFFFu, p1, off);
    }
    if (lane == 0) {
        const float bias = bs[n];
        reinterpret_cast<float*>(g_actv4[b0])[n]     = p0 + bias;
        reinterpret_cast<float*>(g_actv4[b0 + 1])[n] = p1 + bias;
    }
}

// ---------------------------------------------------------------------------
// K2: 256-bit accesses with L2 policy (x/sem evict_last, out evict_first).
// Each thread: 8 contiguous floats. Grid (4,4,16) = 256 blocks x 512 threads.
// ---------------------------------------------------------------------------
__global__ __launch_bounds__(TPB) void main_kernel(
    const float* __restrict__ x,
    const float* __restrict__ sem,
    const float* __restrict__ Wg, const float* __restrict__ bg,
    const float* __restrict__ Wb, const float* __restrict__ bb,
    const float* __restrict__ Wr, const float* __restrict__ br,
    float* __restrict__ out) {
    const int tid  = threadIdx.x;
    const int warp = tid >> 5;
    const int lane = tid & 31;
    const int b    = blockIdx.y;
    const int c0   = blockIdx.z * CCHUNK;
    const int hw8  = blockIdx.x * TPB + tid;   // [0, HWSZ/8)

    __shared__ float s_gw[NUM_OP], s_bw[NUM_OP];
    __shared__ float s_wrsum, s_br;

    // 1) Issue the 6 semantic loads immediately (256-bit, evict_last).
    const float* semb = sem + (size_t)b * SEM_CH * HWSZ + 2 * HWSZ + (size_t)hw8 * 8;
    float4 svlo[NUM_OP], svhi[NUM_OP];
#pragma unroll
    for (int k = 0; k < NUM_OP; ++k)
        ld_el8(semb + (size_t)k * HWSZ, svlo[k], svhi[k]);

    // 2) Fold runs while those LDGs are in flight (warps 0-6 of 16).
    if (warp < NUM_OP) {
        const int k = warp;
        const float4 a  = g_actv4[b][lane];
        const float4 wg = reinterpret_cast<const float4*>(Wg)[(size_t)k * (NHIDDEN / 4) + lane];
        const float4 wb = reinterpret_cast<const float4*>(Wb)[(size_t)k * (NHIDDEN / 4) + lane];
        float pg = dot4(a, wg);
        float pb = dot4(a, wb);
#pragma unroll
        for (int off = 16; off > 0; off >>= 1) {
            pg += __shfl_xor_sync(0xFFFFFFFFu, pg, off);
            pb += __shfl_xor_sync(0xFFFFFFFFu, pb, off);
        }
        if (lane == 0) {
            const float wr = Wr[k];
            s_gw[k] = (pg + bg[k]) * wr;
            s_bw[k] = (pb + bb[k]) * wr;
        }
    } else if (warp == 6 && lane == 0) {
        float s = 0.0f;
#pragma unroll
        for (int k = 0; k < NUM_OP; ++k) s += Wr[k];
        s_wrsum = s;
        s_br = br[0];
    }
    __syncthreads();   // drains smem stores; outstanding LDGs keep flying

    // 3) Combine into 8-wide scale/shift.
    float4 sclo = make_float4(s_wrsum, s_wrsum, s_wrsum, s_wrsum), schi = sclo;
    float4 shlo = make_float4(s_br, s_br, s_br, s_br),            shhi = shlo;
#pragma unroll
    for (int k = 0; k < NUM_OP; ++k) {
        const float gw = s_gw[k];
        const float bw = s_bw[k];
        sclo.x += gw * svlo[k].x;  sclo.y += gw * svlo[k].y;
        sclo.z += gw * svlo[k].z;  sclo.w += gw * svlo[k].w;
        schi.x += gw * svhi[k].x;  schi.y += gw * svhi[k].y;
        schi.z += gw * svhi[k].z;  schi.w += gw * svhi[k].w;
        shlo.x += bw * svlo[k].x;  shlo.y += bw * svlo[k].y;
        shlo.z += bw * svlo[k].z;  shlo.w += bw * svlo[k].w;
        shhi.x += bw * svhi[k].x;  shhi.y += bw * svhi[k].y;
        shhi.z += bw * svhi[k].z;  shhi.w += bw * svhi[k].w;
    }

    // 4) Stream CCHUNK channels: 256-bit evict_last reads, evict_first writes.
    const float* xb = x   + (size_t)b * NC * HWSZ + (size_t)hw8 * 8;
    float*       ob = out + (size_t)b * NC * HWSZ + (size_t)hw8 * 8;

#pragma unroll
    for (int c = c0; c < c0 + CCHUNK; ++c) {
        float4 xlo, xhi;
        ld_el8(xb + (size_t)c * HWSZ, xlo, xhi);
        float4 olo, ohi;
        olo.x = xlo.x * sclo.x + shlo.x;  olo.y = xlo.y * sclo.y + shlo.y;
        olo.z = xlo.z * sclo.z + shlo.z;  olo.w = xlo.w * sclo.w + shlo.w;
        ohi.x = xhi.x * schi.x + shhi.x;  ohi.y = xhi.y * schi.y + shhi.y;
        ohi.z = xhi.z * schi.z + shhi.z;  ohi.w = xhi.w * schi.w + shhi.w;
        st_ef8(ob + (size_t)c * HWSZ, olo, ohi);
    }
}

// ---------------------------------------------------------------------------
extern "C" void kernel_launch(void* const* d_in, const int* in_sizes, int n_in,
                              void* d_out, int out_size) {
    const float* x    = (const float*)d_in[0];
    const float* lang = (const float*)d_in[1];
    const float* sem  = (const float*)d_in[2];
    const float* Ws   = (const float*)d_in[3];
    const float* bs   = (const float*)d_in[4];
    const float* Wg   = (const float*)d_in[5];
    const float* bg   = (const float*)d_in[6];
    const float* Wb   = (const float*)d_in[7];
    const float* bb   = (const float*)d_in[8];
    const float* Wr   = (const float*)d_in[9];
    const float* br   = (const float*)d_in[10];
    float* out = (float*)d_out;

    actv_kernel<<<32, 256>>>(lang, Ws, bs);

    dim3 grid(GRID_X, NB, GRID_Z);
    main_kernel<<<grid, TPB>>>(x, sem, Wg, bg, Wb, bb, Wr, br, out);
}

// round 16
// speedup vs baseline: 1.1425x; 1.0356x over previous
#include <cuda_runtime.h>

#define NB 4
#define NUM_OP 6
#define LANG_DIM 256
#define NHIDDEN 128
#define HH 128
#define WW 128
#define HWSZ (HH * WW)        // 16384
#define NC 128
#define SEM_CH (NUM_OP + 2)   // 8

#define CCHUNK 16
#define TPB 512
#define GRID_X (HWSZ / 4 / TPB)     // 8
#define GRID_Z (NC / CCHUNK)        // 8   -> 256 blocks x 512 threads

__device__ float4 g_actv4[NB][NHIDDEN / 4];

__device__ __forceinline__ float dot4(float4 a, float4 b) {
    return a.x * b.x + a.y * b.y + a.z * b.z + a.w * b.w;
}

// ---------------------------------------------------------------------------
// K1: actv[b][n] = bs[n] + lang[b,:].Ws[n,:]  — 32 blocks x 256 threads.
// Block q, warp w: row n = 4q + (w>>1), batch pair b0 = (w&1)*2.
// Each block reads 4 KB of Ws (float4, coalesced); Ws read once chip-wide.
// ---------------------------------------------------------------------------
__global__ __launch_bounds__(256) void actv_kernel(
    const float* __restrict__ lang,
    const float* __restrict__ Ws, const float* __restrict__ bs) {
    const int warp = threadIdx.x >> 5;
    const int lane = threadIdx.x & 31;
    const int n  = 4 * blockIdx.x + (warp >> 1);
    const int b0 = (warp & 1) * 2;

    const float4* Ws4   = reinterpret_cast<const float4*>(Ws) + (size_t)n * (LANG_DIM / 4);
    const float4* lang4 = reinterpret_cast<const float4*>(lang);

    float p0 = 0.0f, p1 = 0.0f;
#pragma unroll
    for (int i = 0; i < 2; ++i) {
        const int idx = lane + 32 * i;
        const float4 wv = Ws4[idx];
        p0 += dot4(wv, lang4[(size_t)b0 * (LANG_DIM / 4) + idx]);
        p1 += dot4(wv, lang4[(size_t)(b0 + 1) * (LANG_DIM / 4) + idx]);
    }
#pragma unroll
    for (int off = 16; off > 0; off >>= 1) {
        p0 += __shfl_xor_sync(0xFFFFFFFFu, p0, off);
        p1 += __shfl_xor_sync(0xFFFFFFFFu, p1, off);
    }
    if (lane == 0) {
        const float bias = bs[n];
        reinterpret_cast<float*>(g_actv4[b0])[n]     = p0 + bias;
        reinterpret_cast<float*>(g_actv4[b0 + 1])[n] = p1 + bias;
    }
}

// ---------------------------------------------------------------------------
// K2: 512-thread blocks -> 8 KB contiguous DRAM span per channel-chunk.
// sem loads issued first, fold overlapped under their latency, then stream.
// Grid (8,4,8) = 256 blocks x 512 threads.
// ---------------------------------------------------------------------------
__global__ __launch_bounds__(TPB) void main_kernel(
    const float* __restrict__ x,
    const float* __restrict__ sem,
    const float* __restrict__ Wg, const float* __restrict__ bg,
    const float* __restrict__ Wb, const float* __restrict__ bb,
    const float* __restrict__ Wr, const float* __restrict__ br,
    float* __restrict__ out) {
    const int tid  = threadIdx.x;
    const int warp = tid >> 5;
    const int lane = tid & 31;
    const int b    = blockIdx.y;
    const int c0   = blockIdx.z * CCHUNK;
    const int hw4  = blockIdx.x * TPB + tid;   // [0, HWSZ/4)

    __shared__ float s_gw[NUM_OP], s_bw[NUM_OP];
    __shared__ float s_wrsum, s_br;

    // 1) Issue the 6 semantic loads immediately (independent of coefficients).
    const float4* semb =
        reinterpret_cast<const float4*>(sem + (size_t)b * SEM_CH * HWSZ + 2 * HWSZ) + hw4;
    float4 sv[NUM_OP];
#pragma unroll
    for (int k = 0; k < NUM_OP; ++k)
        sv[k] = __ldg(semb + (size_t)k * (HWSZ / 4));

    // 2) Fold runs while those LDGs are in flight (warps 0-6 of 16).
    if (warp < NUM_OP) {
        const int k = warp;
        const float4 a  = g_actv4[b][lane];
        const float4 wg = reinterpret_cast<const float4*>(Wg)[(size_t)k * (NHIDDEN / 4) + lane];
        const float4 wb = reinterpret_cast<const float4*>(Wb)[(size_t)k * (NHIDDEN / 4) + lane];
        float pg = dot4(a, wg);
        float pb = dot4(a, wb);
#pragma unroll
        for (int off = 16; off > 0; off >>= 1) {
            pg += __shfl_xor_sync(0xFFFFFFFFu, pg, off);
            pb += __shfl_xor_sync(0xFFFFFFFFu, pb, off);
        }
        if (lane == 0) {
            const float wr = Wr[k];
            s_gw[k] = (pg + bg[k]) * wr;
            s_bw[k] = (pb + bb[k]) * wr;
        }
    } else if (warp == 6 && lane == 0) {
        float s = 0.0f;
#pragma unroll
        for (int k = 0; k < NUM_OP; ++k) s += Wr[k];
        s_wrsum = s;
        s_br = br[0];
    }
    __syncthreads();   // drains smem stores; outstanding LDGs keep flying

    // 3) Combine (first consumption of sv -> scoreboard wait lands here).
    float4 scale = make_float4(s_wrsum, s_wrsum, s_wrsum, s_wrsum);
    float4 shift = make_float4(s_br, s_br, s_br, s_br);
#pragma unroll
    for (int k = 0; k < NUM_OP; ++k) {
        const float gw = s_gw[k];
        const float bw = s_bw[k];
        scale.x += gw * sv[k].x;  scale.y += gw * sv[k].y;
        scale.z += gw * sv[k].z;  scale.w += gw * sv[k].w;
        shift.x += bw * sv[k].x;  shift.y += bw * sv[k].y;
        shift.z += bw * sv[k].z;  shift.w += bw * sv[k].w;
    }

    // 4) Stream 16 channels of x -> out; 8 KB contiguous per channel per block.
    const float4* xb = reinterpret_cast<const float4*>(x + (size_t)b * NC * HWSZ) + hw4;
    float4*       ob = reinterpret_cast<float4*>(out + (size_t)b * NC * HWSZ) + hw4;

#pragma unroll 8
    for (int c = c0; c < c0 + CCHUNK; ++c) {
        float4 xv = xb[(size_t)c * (HWSZ / 4)];
        float4 o;
        o.x = xv.x * scale.x + shift.x;
        o.y = xv.y * scale.y + shift.y;
        o.z = xv.z * scale.z + shift.z;
        o.w = xv.w * scale.w + shift.w;
        ob[(size_t)c * (HWSZ / 4)] = o;
    }
}

// ---------------------------------------------------------------------------
extern "C" void kernel_launch(void* const* d_in, const int* in_sizes, int n_in,
                              void* d_out, int out_size) {
    const float* x    = (const float*)d_in[0];
    const float* lang = (const float*)d_in[1];
    const float* sem  = (const float*)d_in[2];
    const float* Ws   = (const float*)d_in[3];
    const float* bs   = (const float*)d_in[4];
    const float* Wg   = (const float*)d_in[5];
    const float* bg   = (const float*)d_in[6];
    const float* Wb   = (const float*)d_in[7];
    const float* bb   = (const float*)d_in[8];
    const float* Wr   = (const float*)d_in[9];
    const float* br   = (const float*)d_in[10];
    float* out = (float*)d_out;

    actv_kernel<<<32, 256>>>(lang, Ws, bs);

    dim3 grid(GRID_X, NB, GRID_Z);
    main_kernel<<<grid, TPB>>>(x, sem, Wg, bg, Wb, bb, Wr, br, out);
}